// round 1
// baseline (speedup 1.0000x reference)
#include <cuda_runtime.h>
#include <cstdint>

#define N_NODES 50000
#define N_EDGES 800000
#define DIM     128
#define NG      64
#define OUTD    16

// ---------------- scratch (static device globals; no allocation) ----------------
__device__ __align__(16) int   g_src[N_EDGES];
__device__ __align__(16) int   g_dst[N_EDGES];
__device__ __align__(16) int   g_batch[N_NODES];
__device__ __align__(16) float g_deg[N_NODES];
__device__ __align__(16) float g_dis[N_NODES];
__device__ __align__(128) float g_bufA[(size_t)N_NODES * DIM];  // hs (gather source)
__device__ __align__(128) float g_bufB[(size_t)N_NODES * DIM];  // agg / y
__device__ __align__(16) float g_sums[NG * DIM];
__device__ __align__(16) float g_cnts[NG];
__device__ int g_is64;

// ---------------- dtype detection (int64 vs int32 indices) ----------------
__global__ void k_detect(const void* ei) {
    const unsigned long long* p = (const unsigned long long*)ei;
    bool is64 = true;
    for (int i = 0; i < 8; i++)
        if (p[i] >= (unsigned long long)N_NODES) is64 = false;
    g_is64 = is64 ? 1 : 0;
}

__global__ void k_convert(const void* ei, const void* batch) {
    int i  = blockIdx.x * blockDim.x + threadIdx.x;
    int st = gridDim.x * blockDim.x;
    const bool is64 = (g_is64 != 0);
    for (int e = i; e < N_EDGES; e += st) {
        int s, d;
        if (is64) {
            s = (int)((const long long*)ei)[e];
            d = (int)((const long long*)ei)[N_EDGES + e];
        } else {
            s = ((const int*)ei)[e];
            d = ((const int*)ei)[N_EDGES + e];
        }
        g_src[e] = s;
        g_dst[e] = d;
    }
    for (int n = i; n < N_NODES; n += st) {
        g_batch[n] = is64 ? (int)((const long long*)batch)[n]
                          : ((const int*)batch)[n];
    }
}

// ---------------- degree / init ----------------
__global__ void k_init() {
    int i  = blockIdx.x * blockDim.x + threadIdx.x;
    int st = gridDim.x * blockDim.x;
    for (int n = i; n < N_NODES; n += st) g_deg[n] = 1.0f;  // self loop
    for (int n = i; n < NG * DIM; n += st) g_sums[n] = 0.0f;
    for (int n = i; n < NG; n += st) g_cnts[n] = 0.0f;
}

__global__ void k_degadd() {
    int i  = blockIdx.x * blockDim.x + threadIdx.x;
    int st = gridDim.x * blockDim.x;
    for (int e = i; e < N_EDGES; e += st)
        atomicAdd(&g_deg[g_dst[e]], 1.0f);
}

__global__ void k_dis() {
    int i  = blockIdx.x * blockDim.x + threadIdx.x;
    int st = gridDim.x * blockDim.x;
    for (int n = i; n < N_NODES; n += st)
        g_dis[n] = rsqrtf(g_deg[n]);  // deg >= 1 always
}

// ---------------- GEMM: C = (A @ W) * dis[row], written to BOTH bufA and bufB ----------------
// A: [M,128] row-major (if Ain==nullptr, read g_bufB; in-place safe: each block
// reads only its own 128 rows across the whole K loop, then writes them).
// W: [128,128] row-major.
__global__ __launch_bounds__(256) void k_gemm(const float* Ain, const float* __restrict__ W) {
    __shared__ float As[16][132];  // k-major, padded
    __shared__ float Bs[16][132];
    const float* A = Ain ? Ain : g_bufB;
    const int tid  = threadIdx.x;
    const int tx   = tid & 15;
    const int ty   = tid >> 4;
    const int row0 = blockIdx.x * 128;

    float acc[8][8];
#pragma unroll
    for (int i = 0; i < 8; i++)
#pragma unroll
        for (int j = 0; j < 8; j++) acc[i][j] = 0.0f;

    for (int kt = 0; kt < 128; kt += 16) {
        // load A tile: 128 rows x 16 k  (512 float4s, 2 per thread)
#pragma unroll
        for (int l = 0; l < 2; l++) {
            int idx = tid + l * 256;          // 0..511
            int r   = idx >> 2;               // 0..127
            int kk  = (idx & 3) * 4;          // 0,4,8,12
            float4 v = make_float4(0.f, 0.f, 0.f, 0.f);
            int gr = row0 + r;
            if (gr < N_NODES) v = *(const float4*)&A[(size_t)gr * DIM + kt + kk];
            As[kk + 0][r] = v.x;
            As[kk + 1][r] = v.y;
            As[kk + 2][r] = v.z;
            As[kk + 3][r] = v.w;
        }
        // load B tile: W[kt..kt+16][0..127]
#pragma unroll
        for (int l = 0; l < 2; l++) {
            int idx = tid + l * 256;
            int k   = idx >> 5;               // 0..15
            int c   = (idx & 31) * 4;         // 0..124
            float4 v = *(const float4*)&W[(size_t)(kt + k) * DIM + c];
            Bs[k][c + 0] = v.x;
            Bs[k][c + 1] = v.y;
            Bs[k][c + 2] = v.z;
            Bs[k][c + 3] = v.w;
        }
        __syncthreads();
#pragma unroll
        for (int k = 0; k < 16; k++) {
            const float4 a0 = *(const float4*)&As[k][ty * 8];
            const float4 a1 = *(const float4*)&As[k][ty * 8 + 4];
            const float4 b0 = *(const float4*)&Bs[k][tx * 8];
            const float4 b1 = *(const float4*)&Bs[k][tx * 8 + 4];
            const float a[8] = {a0.x, a0.y, a0.z, a0.w, a1.x, a1.y, a1.z, a1.w};
            const float b[8] = {b0.x, b0.y, b0.z, b0.w, b1.x, b1.y, b1.z, b1.w};
#pragma unroll
            for (int i = 0; i < 8; i++)
#pragma unroll
                for (int j = 0; j < 8; j++) acc[i][j] += a[i] * b[j];
        }
        __syncthreads();
    }

    // epilogue: scale by dis[row], write both buffers
#pragma unroll
    for (int i = 0; i < 8; i++) {
        int gr = row0 + ty * 8 + i;
        if (gr < N_NODES) {
            float s = g_dis[gr];
#pragma unroll
            for (int j = 0; j < 8; j += 4) {
                float4 v;
                v.x = acc[i][j + 0] * s;
                v.y = acc[i][j + 1] * s;
                v.z = acc[i][j + 2] * s;
                v.w = acc[i][j + 3] * s;
                size_t off = (size_t)gr * DIM + tx * 8 + j;
                *(float4*)&g_bufA[off] = v;
                *(float4*)&g_bufB[off] = v;
            }
        }
    }
}

// ---------------- edge scatter: bufB[dst] += bufA[src] (warp per edge, RED.128) ----------------
__device__ __forceinline__ void red_add_v4(float* p, float4 v) {
    unsigned long long gp = (unsigned long long)__cvta_generic_to_global(p);
    asm volatile("red.global.add.v4.f32 [%0], {%1,%2,%3,%4};"
                 :: "l"(gp), "f"(v.x), "f"(v.y), "f"(v.z), "f"(v.w)
                 : "memory");
}

__global__ void k_scatter() {
    int gtid = blockIdx.x * blockDim.x + threadIdx.x;
    int warp = gtid >> 5;
    int lane = gtid & 31;
    int nw   = (gridDim.x * blockDim.x) >> 5;
    for (int e = warp; e < N_EDGES; e += nw) {
        int s = g_src[e];
        int d = g_dst[e];
        float4 v = *(const float4*)&g_bufA[(size_t)s * DIM + lane * 4];
        red_add_v4(&g_bufB[(size_t)d * DIM + lane * 4], v);
    }
}

// ---------------- finalize: y = relu(agg * dis + b) in-place on bufB ----------------
__global__ void k_finalize(const float* __restrict__ bias) {
    int i  = blockIdx.x * blockDim.x + threadIdx.x;
    int st = gridDim.x * blockDim.x;
    const int total = N_NODES * (DIM / 4);
    for (int t = i; t < total; t += st) {
        int n  = t >> 5;
        int c4 = (t & 31) * 4;
        float s = g_dis[n];
        size_t off = (size_t)n * DIM + c4;
        float4 v = *(float4*)&g_bufB[off];
        float4 b = *(const float4*)&bias[c4];
        v.x = fmaxf(fmaf(v.x, s, b.x), 0.0f);
        v.y = fmaxf(fmaf(v.y, s, b.y), 0.0f);
        v.z = fmaxf(fmaf(v.z, s, b.z), 0.0f);
        v.w = fmaxf(fmaf(v.w, s, b.w), 0.0f);
        *(float4*)&g_bufB[off] = v;
    }
}

// ---------------- mean pool: sums[g] += y[n], cnts[g] += 1 ----------------
__global__ void k_pool() {
    int gtid = blockIdx.x * blockDim.x + threadIdx.x;
    int warp = gtid >> 5;
    int lane = gtid & 31;
    int nw   = (gridDim.x * blockDim.x) >> 5;
    for (int n = warp; n < N_NODES; n += nw) {
        int g = g_batch[n];
        float4 v = *(const float4*)&g_bufB[(size_t)n * DIM + lane * 4];
        red_add_v4(&g_sums[g * DIM + lane * 4], v);
        if (lane == 0) atomicAdd(&g_cnts[g], 1.0f);
    }
}

// ---------------- final FC: out[g,o] = (sums[g]/cnt) @ Wfc + bfc ----------------
__global__ void k_final(const float* __restrict__ Wfc, const float* __restrict__ bfc,
                        float* __restrict__ out) {
    int idx = blockIdx.x * blockDim.x + threadIdx.x;
    if (idx >= NG * OUTD) return;
    int g = idx / OUTD;
    int o = idx % OUTD;
    float inv = 1.0f / fmaxf(g_cnts[g], 1.0f);
    float acc = 0.0f;
#pragma unroll 8
    for (int h = 0; h < DIM; h++) acc += g_sums[g * DIM + h] * Wfc[h * OUTD + o];
    out[idx] = acc * inv + bfc[o];
}

// ---------------- launch ----------------
extern "C" void kernel_launch(void* const* d_in, const int* in_sizes, int n_in,
                              void* d_out, int out_size) {
    const float* x     = (const float*)d_in[0];
    const void*  ei    = d_in[1];
    const void*  batch = d_in[2];
    const float* W1    = (const float*)d_in[3];
    const float* b1    = (const float*)d_in[4];
    const float* W2    = (const float*)d_in[5];
    const float* b2    = (const float*)d_in[6];
    const float* Wfc   = (const float*)d_in[7];
    const float* bfc   = (const float*)d_in[8];
    float* out = (float*)d_out;

    const int gemm_blocks = (N_NODES + 127) / 128;  // 391

    k_detect<<<1, 1>>>(ei);
    k_convert<<<1024, 256>>>(ei, batch);
    k_init<<<256, 256>>>();
    k_degadd<<<1024, 256>>>();
    k_dis<<<256, 256>>>();

    // layer 1
    k_gemm<<<gemm_blocks, 256>>>(x, W1);
    k_scatter<<<2368, 256>>>();
    k_finalize<<<1184, 256>>>(b1);

    // layer 2 (gemm reads bufB, writes bufA+bufB; per-block in-place safe)
    k_gemm<<<gemm_blocks, 256>>>(nullptr, W2);
    k_scatter<<<2368, 256>>>();
    k_finalize<<<1184, 256>>>(b2);

    // pool + fc
    k_pool<<<1184, 256>>>();
    k_final<<<4, 256>>>(Wfc, bfc, out);
}

// round 4
// speedup vs baseline: 1.3221x; 1.3221x over previous
#include <cuda_runtime.h>
#include <cstdint>

#define N_NODES 50000
#define N_EDGES 800000
#define DIM     128
#define NG      64
#define OUTD    16
#define SCAN_B  1024
#define NBLK    ((N_NODES + SCAN_B - 1) / SCAN_B)   // 49

// ---------------- scratch (static device globals; no allocation) ----------------
__device__ __align__(16) int   g_src[N_EDGES];
__device__ __align__(16) int   g_dst[N_EDGES];
__device__ __align__(16) int   g_esrc[N_EDGES];     // bucketed-by-dst src list
__device__ __align__(16) int   g_batch[N_NODES];
__device__ __align__(16) int   g_ecnt[N_NODES];     // in-degree (edges only)
__device__ __align__(16) int   g_off[N_NODES];      // block-local exclusive scan
__device__ __align__(16) int   g_rowstart[N_NODES]; // final CSR row start
__device__ __align__(16) int   g_cursor[N_NODES];   // bucket-fill cursors
__device__ int   g_bsum[NBLK];
__device__ int   g_bo[NBLK];
__device__ __align__(16) float g_dis[N_NODES];
__device__ __align__(128) float g_bufA[(size_t)N_NODES * DIM];  // h*dis (gather source)
__device__ __align__(128) float g_bufB[(size_t)N_NODES * DIM];  // layer output
__device__ __align__(16) float g_sums[NG * DIM];
__device__ __align__(16) float g_cnts[NG];
__device__ int g_is64;

// ---------------- dtype detection (int64 vs int32 indices) ----------------
__global__ void k_detect(const void* ei) {
    const unsigned long long* p = (const unsigned long long*)ei;
    bool is64 = true;
    for (int i = 0; i < 8; i++)
        if (p[i] >= (unsigned long long)N_NODES) is64 = false;
    g_is64 = is64 ? 1 : 0;
}

// ---------------- init: zero counters ----------------
__global__ void k_init() {
    int i  = blockIdx.x * blockDim.x + threadIdx.x;
    int st = gridDim.x * blockDim.x;
    for (int n = i; n < N_NODES; n += st) g_ecnt[n] = 0;
    for (int n = i; n < NG * DIM; n += st) g_sums[n] = 0.0f;
    for (int n = i; n < NG; n += st) g_cnts[n] = 0.0f;
}

// ---------------- convert indices + degree histogram + graph counts ----------------
__global__ void k_convert(const void* ei, const void* batch) {
    int i  = blockIdx.x * blockDim.x + threadIdx.x;
    int st = gridDim.x * blockDim.x;
    const bool is64 = (g_is64 != 0);
    for (int e = i; e < N_EDGES; e += st) {
        int s, d;
        if (is64) {
            s = (int)((const long long*)ei)[e];
            d = (int)((const long long*)ei)[N_EDGES + e];
        } else {
            s = ((const int*)ei)[e];
            d = ((const int*)ei)[N_EDGES + e];
        }
        g_src[e] = s;
        g_dst[e] = d;
        atomicAdd(&g_ecnt[d], 1);
    }
    for (int n = i; n < N_NODES; n += st) {
        int b = is64 ? (int)((const long long*)batch)[n]
                     : ((const int*)batch)[n];
        g_batch[n] = b;
        atomicAdd(&g_cnts[b], 1.0f);
    }
}

// ---------------- dis = rsqrt(deg), deg = ecnt + 1 (self loop) ----------------
__global__ void k_dis() {
    int i  = blockIdx.x * blockDim.x + threadIdx.x;
    int st = gridDim.x * blockDim.x;
    for (int n = i; n < N_NODES; n += st)
        g_dis[n] = rsqrtf((float)(g_ecnt[n] + 1));
}

// ---------------- scan phase 1: per-block exclusive scan of ecnt ----------------
__global__ __launch_bounds__(SCAN_B) void k_scan1() {
    __shared__ int sh[SCAN_B];
    int b = blockIdx.x, t = threadIdx.x;
    int i = b * SCAN_B + t;
    int v = (i < N_NODES) ? g_ecnt[i] : 0;
    sh[t] = v;
    __syncthreads();
    for (int s = 1; s < SCAN_B; s <<= 1) {
        int x = (t >= s) ? sh[t - s] : 0;
        __syncthreads();
        sh[t] += x;
        __syncthreads();
    }
    if (i < N_NODES) g_off[i] = sh[t] - v;   // exclusive
    if (t == SCAN_B - 1) g_bsum[b] = sh[t];
}

// ---------------- scan phase 2: scan block sums (tiny) ----------------
__global__ void k_scan2() {
    if (threadIdx.x == 0) {
        int a = 0;
        for (int i = 0; i < NBLK; i++) { g_bo[i] = a; a += g_bsum[i]; }
    }
}

// ---------------- scan phase 3: final offsets + cursor init ----------------
__global__ void k_cursor() {
    int i  = blockIdx.x * blockDim.x + threadIdx.x;
    int st = gridDim.x * blockDim.x;
    for (int n = i; n < N_NODES; n += st) {
        int base = g_off[n] + g_bo[n >> 10];
        g_rowstart[n] = base;
        g_cursor[n]   = base;
    }
}

// ---------------- bucket fill: group edge srcs by dst ----------------
__global__ void k_bucket() {
    int i  = blockIdx.x * blockDim.x + threadIdx.x;
    int st = gridDim.x * blockDim.x;
    for (int e = i; e < N_EDGES; e += st) {
        int d = g_dst[e];
        int pos = atomicAdd(&g_cursor[d], 1);
        g_esrc[pos] = g_src[e];
    }
}

// ---------------- GEMM: bufA = (A @ W) * dis[row] ----------------
// Ain==nullptr -> read g_bufB (device-side symbol resolution; passing the
// __device__ symbol from host code is invalid and was the R2 bug).
__global__ __launch_bounds__(256) void k_gemm(const float* Ain,
                                              const float* __restrict__ W) {
    __shared__ float As[16][132];  // k-major, padded
    __shared__ float Bs[16][132];
    const float* A = Ain ? Ain : g_bufB;
    const int tid  = threadIdx.x;
    const int tx   = tid & 15;
    const int ty   = tid >> 4;
    const int row0 = blockIdx.x * 128;

    float acc[8][8];
#pragma unroll
    for (int i = 0; i < 8; i++)
#pragma unroll
        for (int j = 0; j < 8; j++) acc[i][j] = 0.0f;

    for (int kt = 0; kt < 128; kt += 16) {
#pragma unroll
        for (int l = 0; l < 2; l++) {
            int idx = tid + l * 256;          // 0..511
            int r   = idx >> 2;               // 0..127
            int kk  = (idx & 3) * 4;          // 0,4,8,12
            float4 v = make_float4(0.f, 0.f, 0.f, 0.f);
            int gr = row0 + r;
            if (gr < N_NODES) v = *(const float4*)&A[(size_t)gr * DIM + kt + kk];
            As[kk + 0][r] = v.x;
            As[kk + 1][r] = v.y;
            As[kk + 2][r] = v.z;
            As[kk + 3][r] = v.w;
        }
#pragma unroll
        for (int l = 0; l < 2; l++) {
            int idx = tid + l * 256;
            int k   = idx >> 5;               // 0..15
            int c   = (idx & 31) * 4;         // 0..124
            float4 v = *(const float4*)&W[(size_t)(kt + k) * DIM + c];
            Bs[k][c + 0] = v.x;
            Bs[k][c + 1] = v.y;
            Bs[k][c + 2] = v.z;
            Bs[k][c + 3] = v.w;
        }
        __syncthreads();
#pragma unroll
        for (int k = 0; k < 16; k++) {
            const float4 a0 = *(const float4*)&As[k][ty * 8];
            const float4 a1 = *(const float4*)&As[k][ty * 8 + 4];
            const float4 b0 = *(const float4*)&Bs[k][tx * 8];
            const float4 b1 = *(const float4*)&Bs[k][tx * 8 + 4];
            const float a[8] = {a0.x, a0.y, a0.z, a0.w, a1.x, a1.y, a1.z, a1.w};
            const float b[8] = {b0.x, b0.y, b0.z, b0.w, b1.x, b1.y, b1.z, b1.w};
#pragma unroll
            for (int i = 0; i < 8; i++)
#pragma unroll
                for (int j = 0; j < 8; j++) acc[i][j] += a[i] * b[j];
        }
        __syncthreads();
    }

#pragma unroll
    for (int i = 0; i < 8; i++) {
        int gr = row0 + ty * 8 + i;
        if (gr < N_NODES) {
            float s = g_dis[gr];
#pragma unroll
            for (int j = 0; j < 8; j += 4) {
                float4 v;
                v.x = acc[i][j + 0] * s;
                v.y = acc[i][j + 1] * s;
                v.z = acc[i][j + 2] * s;
                v.w = acc[i][j + 3] * s;
                *(float4*)&g_bufA[(size_t)gr * DIM + tx * 8 + j] = v;
            }
        }
    }
}

// ---------------- RED.v4 helper ----------------
__device__ __forceinline__ void red_add_v4(float* p, float4 v) {
    unsigned long long gp = (unsigned long long)__cvta_generic_to_global(p);
    asm volatile("red.global.add.v4.f32 [%0], {%1,%2,%3,%4};"
                 :: "l"(gp), "f"(v.x), "f"(v.y), "f"(v.z), "f"(v.w)
                 : "memory");
}

// ---------------- aggregation: warp per node, CSR gather ----------------
// bufB[n] = relu(dis[n] * (bufA[n] + sum_{s in bucket(n)} bufA[s]) + bias)
// POOL: also RED into g_sums[batch[n]].
template <bool POOL>
__global__ __launch_bounds__(256) void k_agg(const float* __restrict__ bias) {
    int gtid = blockIdx.x * blockDim.x + threadIdx.x;
    int warp = gtid >> 5;
    int lane = gtid & 31;
    int nw   = (gridDim.x * blockDim.x) >> 5;
    float4 b = *(const float4*)&bias[lane * 4];

    for (int n = warp; n < N_NODES; n += nw) {
        int start = g_rowstart[n];
        int cnt   = g_ecnt[n];
        // self loop
        float4 acc = *(const float4*)&g_bufA[(size_t)n * DIM + lane * 4];

        int k = 0;
        for (; k + 4 <= cnt; k += 4) {
            int s0 = g_esrc[start + k + 0];
            int s1 = g_esrc[start + k + 1];
            int s2 = g_esrc[start + k + 2];
            int s3 = g_esrc[start + k + 3];
            float4 v0 = *(const float4*)&g_bufA[(size_t)s0 * DIM + lane * 4];
            float4 v1 = *(const float4*)&g_bufA[(size_t)s1 * DIM + lane * 4];
            float4 v2 = *(const float4*)&g_bufA[(size_t)s2 * DIM + lane * 4];
            float4 v3 = *(const float4*)&g_bufA[(size_t)s3 * DIM + lane * 4];
            acc.x += v0.x + v1.x + v2.x + v3.x;
            acc.y += v0.y + v1.y + v2.y + v3.y;
            acc.z += v0.z + v1.z + v2.z + v3.z;
            acc.w += v0.w + v1.w + v2.w + v3.w;
        }
        for (; k < cnt; k++) {
            int s = g_esrc[start + k];
            float4 v = *(const float4*)&g_bufA[(size_t)s * DIM + lane * 4];
            acc.x += v.x; acc.y += v.y; acc.z += v.z; acc.w += v.w;
        }

        float di = g_dis[n];
        float4 o;
        o.x = fmaxf(fmaf(acc.x, di, b.x), 0.0f);
        o.y = fmaxf(fmaf(acc.y, di, b.y), 0.0f);
        o.z = fmaxf(fmaf(acc.z, di, b.z), 0.0f);
        o.w = fmaxf(fmaf(acc.w, di, b.w), 0.0f);
        *(float4*)&g_bufB[(size_t)n * DIM + lane * 4] = o;

        if (POOL) {
            int g = g_batch[n];
            red_add_v4(&g_sums[g * DIM + lane * 4], o);
        }
    }
}

// ---------------- final FC: out[g,o] = (sums[g]/cnt) @ Wfc + bfc ----------------
__global__ void k_final(const float* __restrict__ Wfc, const float* __restrict__ bfc,
                        float* __restrict__ out) {
    int idx = blockIdx.x * blockDim.x + threadIdx.x;
    if (idx >= NG * OUTD) return;
    int g = idx / OUTD;
    int o = idx % OUTD;
    float inv = 1.0f / fmaxf(g_cnts[g], 1.0f);
    float acc = 0.0f;
#pragma unroll 8
    for (int h = 0; h < DIM; h++) acc += g_sums[g * DIM + h] * Wfc[h * OUTD + o];
    out[idx] = acc * inv + bfc[o];
}

// ---------------- launch ----------------
extern "C" void kernel_launch(void* const* d_in, const int* in_sizes, int n_in,
                              void* d_out, int out_size) {
    const float* x     = (const float*)d_in[0];
    const void*  ei    = d_in[1];
    const void*  batch = d_in[2];
    const float* W1    = (const float*)d_in[3];
    const float* b1    = (const float*)d_in[4];
    const float* W2    = (const float*)d_in[5];
    const float* b2    = (const float*)d_in[6];
    const float* Wfc   = (const float*)d_in[7];
    const float* bfc   = (const float*)d_in[8];
    float* out = (float*)d_out;

    const int gemm_blocks = (N_NODES + 127) / 128;  // 391

    k_detect<<<1, 1>>>(ei);
    k_init<<<256, 256>>>();
    k_convert<<<1024, 256>>>(ei, batch);
    k_dis<<<128, 256>>>();
    k_scan1<<<NBLK, SCAN_B>>>();
    k_scan2<<<1, 32>>>();
    k_cursor<<<128, 256>>>();
    k_bucket<<<1024, 256>>>();

    // layer 1
    k_gemm<<<gemm_blocks, 256>>>(x, W1);
    k_agg<false><<<2368, 256>>>(b1);

    // layer 2 (nullptr -> k_gemm reads g_bufB device-side)
    k_gemm<<<gemm_blocks, 256>>>(nullptr, W2);
    k_agg<true><<<2368, 256>>>(b2);

    k_final<<<4, 256>>>(Wfc, bfc, out);
}

// round 7
// speedup vs baseline: 1.5928x; 1.2047x over previous
#include <cuda_runtime.h>
#include <cstdint>

#define N_NODES 50000
#define N_EDGES 800000
#define DIM     128
#define NG      64
#define OUTD    16
#define SCAN_B  1024
#define NBLK    ((N_NODES + SCAN_B - 1) / SCAN_B)   // 49

// ---------------- scratch (static device globals; no allocation) ----------------
__device__ __align__(16) int   g_src[N_EDGES];
__device__ __align__(16) int   g_dst[N_EDGES];
__device__ __align__(16) int   g_esrc[N_EDGES];     // bucketed-by-dst src list
__device__ __align__(16) int   g_batch[N_NODES];
__device__ __align__(16) int   g_ecnt[N_NODES];     // in-degree (edges only)
__device__ __align__(16) int   g_off[N_NODES];      // block-local exclusive scan
__device__ __align__(16) int   g_rowstart[N_NODES]; // final CSR row start
__device__ __align__(16) int   g_cursor[N_NODES];   // bucket-fill cursors
__device__ int   g_bsum[NBLK];
__device__ int   g_bo[NBLK];
__device__ __align__(128) float g_bufA[(size_t)N_NODES * DIM];  // h*dis (gather source)
__device__ __align__(128) float g_bufB[(size_t)N_NODES * DIM];  // layer output
__device__ __align__(16) float g_sums[NG * DIM];
__device__ __align__(16) float g_cnts[NG];
__device__ int g_is64;

// ---------------- init + dtype detect ----------------
__global__ void k_init(const void* ei) {
    int i  = blockIdx.x * blockDim.x + threadIdx.x;
    if (i == 0) {
        const unsigned long long* p = (const unsigned long long*)ei;
        bool is64 = true;
        for (int j = 0; j < 8; j++)
            if (p[j] >= (unsigned long long)N_NODES) is64 = false;
        g_is64 = is64 ? 1 : 0;
    }
    int st = gridDim.x * blockDim.x;
    for (int n = i; n < N_NODES; n += st) g_ecnt[n] = 0;
    for (int n = i; n < NG * DIM; n += st) g_sums[n] = 0.0f;
    for (int n = i; n < NG; n += st) g_cnts[n] = 0.0f;
}

// ---------------- convert indices + degree histogram + graph counts ----------------
__global__ void k_convert(const void* ei, const void* batch) {
    int i  = blockIdx.x * blockDim.x + threadIdx.x;
    int st = gridDim.x * blockDim.x;
    const bool is64 = (g_is64 != 0);
    for (int e = i; e < N_EDGES; e += st) {
        int s, d;
        if (is64) {
            s = (int)((const long long*)ei)[e];
            d = (int)((const long long*)ei)[N_EDGES + e];
        } else {
            s = ((const int*)ei)[e];
            d = ((const int*)ei)[N_EDGES + e];
        }
        g_src[e] = s;
        g_dst[e] = d;
        atomicAdd(&g_ecnt[d], 1);
    }
    for (int n = i; n < N_NODES; n += st) {
        int b = is64 ? (int)((const long long*)batch)[n]
                     : ((const int*)batch)[n];
        g_batch[n] = b;
        atomicAdd(&g_cnts[b], 1.0f);
    }
}

// ---------------- scan phase 1: per-block exclusive scan of ecnt ----------------
__global__ __launch_bounds__(SCAN_B) void k_scan1() {
    __shared__ int sh[SCAN_B];
    int b = blockIdx.x, t = threadIdx.x;
    int i = b * SCAN_B + t;
    int v = (i < N_NODES) ? g_ecnt[i] : 0;
    sh[t] = v;
    __syncthreads();
    for (int s = 1; s < SCAN_B; s <<= 1) {
        int x = (t >= s) ? sh[t - s] : 0;
        __syncthreads();
        sh[t] += x;
        __syncthreads();
    }
    if (i < N_NODES) g_off[i] = sh[t] - v;   // exclusive
    if (t == SCAN_B - 1) g_bsum[b] = sh[t];
}

// ---------------- scan phase 2 ----------------
__global__ void k_scan2() {
    if (threadIdx.x == 0) {
        int a = 0;
        for (int i = 0; i < NBLK; i++) { g_bo[i] = a; a += g_bsum[i]; }
    }
}

// ---------------- final offsets + cursors ----------------
__global__ void k_cursor() {
    int i  = blockIdx.x * blockDim.x + threadIdx.x;
    int st = gridDim.x * blockDim.x;
    for (int n = i; n < N_NODES; n += st) {
        int base = g_off[n] + g_bo[n >> 10];
        g_rowstart[n] = base;
        g_cursor[n]   = base;
    }
}

// ---------------- bucket fill ----------------
__global__ void k_bucket() {
    int i  = blockIdx.x * blockDim.x + threadIdx.x;
    int st = gridDim.x * blockDim.x;
    for (int e = i; e < N_EDGES; e += st) {
        int d = g_dst[e];
        int pos = atomicAdd(&g_cursor[d], 1);
        g_esrc[pos] = g_src[e];
    }
}

// ---------------- tf32 helpers ----------------
__device__ __forceinline__ unsigned f2tf32(float f) {
    unsigned u;
    asm("cvt.rna.tf32.f32 %0, %1;" : "=r"(u) : "f"(f));
    return u;
}

__device__ __forceinline__ void mma_tf32(float& c0, float& c1, float& c2, float& c3,
                                         unsigned a0, unsigned a1, unsigned a2, unsigned a3,
                                         unsigned b0, unsigned b1) {
    asm volatile(
        "mma.sync.aligned.m16n8k8.row.col.f32.tf32.tf32.f32 "
        "{%0,%1,%2,%3}, {%4,%5,%6,%7}, {%8,%9}, {%0,%1,%2,%3};"
        : "+f"(c0), "+f"(c1), "+f"(c2), "+f"(c3)
        : "r"(a0), "r"(a1), "r"(a2), "r"(a3), "r"(b0), "r"(b1));
}

// ---------------- GEMM: bufA = (A @ W) * dis[row]  (tf32 tensor cores) ----------------
// 8 warps/block, each warp: 16 rows x 128 cols. W staged in smem as tf32,
// transposed layout Ws[n*132 + k] (stride 132 -> conflict-free B frag loads).
// Ain==nullptr -> read g_bufB (device-side symbol; host can't pass __device__ arrays).
__global__ __launch_bounds__(256) void k_gemm(const float* Ain,
                                              const float* __restrict__ W) {
    extern __shared__ unsigned Ws[];   // 128*132 u32 = 67584 B
    const float* A = Ain ? Ain : g_bufB;
    const int tid  = threadIdx.x;
    const int w    = tid >> 5;
    const int lane = tid & 31;
    const int g    = lane >> 2;   // group 0..7
    const int t    = lane & 3;    // thread-in-group 0..3

    // stage W -> smem (transposed, tf32-converted)
    for (int idx = tid; idx < DIM * DIM / 4; idx += 256) {
        int k = (idx * 4) / DIM;       // row of W
        int n = (idx * 4) % DIM;       // col of W
        float4 v = *(const float4*)&W[(size_t)k * DIM + n];
        Ws[(n + 0) * 132 + k] = f2tf32(v.x);
        Ws[(n + 1) * 132 + k] = f2tf32(v.y);
        Ws[(n + 2) * 132 + k] = f2tf32(v.z);
        Ws[(n + 3) * 132 + k] = f2tf32(v.w);
    }
    __syncthreads();

    const int rowA = blockIdx.x * 128 + w * 16 + g;   // rows g, g+8 of warp tile
    const int rowB = rowA + 8;
    const bool okA = rowA < N_NODES;
    const bool okB = rowB < N_NODES;

    float acc[16][4];
#pragma unroll
    for (int nt = 0; nt < 16; nt++)
#pragma unroll
        for (int j = 0; j < 4; j++) acc[nt][j] = 0.0f;

    const float* rA = A + (size_t)rowA * DIM;
    const float* rB = A + (size_t)rowB * DIM;

    for (int kc = 0; kc < 16; kc++) {
        const int K0 = kc * 8;
        unsigned a0 = okA ? f2tf32(rA[K0 + t])     : 0u;
        unsigned a2 = okA ? f2tf32(rA[K0 + t + 4]) : 0u;
        unsigned a1 = okB ? f2tf32(rB[K0 + t])     : 0u;
        unsigned a3 = okB ? f2tf32(rB[K0 + t + 4]) : 0u;
#pragma unroll
        for (int nt = 0; nt < 16; nt++) {
            unsigned b0 = Ws[(nt * 8 + g) * 132 + K0 + t];
            unsigned b1 = Ws[(nt * 8 + g) * 132 + K0 + t + 4];
            mma_tf32(acc[nt][0], acc[nt][1], acc[nt][2], acc[nt][3],
                     a0, a1, a2, a3, b0, b1);
        }
    }

    // epilogue: scale by dis = rsqrt(deg), deg = ecnt + 1
    float disA = okA ? rsqrtf((float)(g_ecnt[rowA] + 1)) : 0.0f;
    float disB = okB ? rsqrtf((float)(g_ecnt[rowB] + 1)) : 0.0f;
#pragma unroll
    for (int nt = 0; nt < 16; nt++) {
        int col = nt * 8 + 2 * t;
        if (okA) {
            float2 v = make_float2(acc[nt][0] * disA, acc[nt][1] * disA);
            *(float2*)&g_bufA[(size_t)rowA * DIM + col] = v;
        }
        if (okB) {
            float2 v = make_float2(acc[nt][2] * disB, acc[nt][3] * disB);
            *(float2*)&g_bufA[(size_t)rowB * DIM + col] = v;
        }
    }
}

// ---------------- RED.v4 helper ----------------
__device__ __forceinline__ void red_add_v4(float* p, float4 v) {
    unsigned long long gp = (unsigned long long)__cvta_generic_to_global(p);
    asm volatile("red.global.add.v4.f32 [%0], {%1,%2,%3,%4};"
                 :: "l"(gp), "f"(v.x), "f"(v.y), "f"(v.z), "f"(v.w)
                 : "memory");
}

// ---------------- aggregation: warp per node, CSR gather ----------------
template <bool POOL>
__global__ __launch_bounds__(256) void k_agg(const float* __restrict__ bias) {
    int gtid = blockIdx.x * blockDim.x + threadIdx.x;
    int warp = gtid >> 5;
    int lane = gtid & 31;
    int nw   = (gridDim.x * blockDim.x) >> 5;
    float4 b = *(const float4*)&bias[lane * 4];

    for (int n = warp; n < N_NODES; n += nw) {
        int start = g_rowstart[n];
        int cnt   = g_ecnt[n];
        float4 acc = *(const float4*)&g_bufA[(size_t)n * DIM + lane * 4];  // self loop

        int k = 0;
        for (; k + 8 <= cnt; k += 8) {
            int s0 = g_esrc[start + k + 0];
            int s1 = g_esrc[start + k + 1];
            int s2 = g_esrc[start + k + 2];
            int s3 = g_esrc[start + k + 3];
            int s4 = g_esrc[start + k + 4];
            int s5 = g_esrc[start + k + 5];
            int s6 = g_esrc[start + k + 6];
            int s7 = g_esrc[start + k + 7];
            float4 v0 = *(const float4*)&g_bufA[(size_t)s0 * DIM + lane * 4];
            float4 v1 = *(const float4*)&g_bufA[(size_t)s1 * DIM + lane * 4];
            float4 v2 = *(const float4*)&g_bufA[(size_t)s2 * DIM + lane * 4];
            float4 v3 = *(const float4*)&g_bufA[(size_t)s3 * DIM + lane * 4];
            float4 v4 = *(const float4*)&g_bufA[(size_t)s4 * DIM + lane * 4];
            float4 v5 = *(const float4*)&g_bufA[(size_t)s5 * DIM + lane * 4];
            float4 v6 = *(const float4*)&g_bufA[(size_t)s6 * DIM + lane * 4];
            float4 v7 = *(const float4*)&g_bufA[(size_t)s7 * DIM + lane * 4];
            acc.x += (v0.x + v1.x) + (v2.x + v3.x) + ((v4.x + v5.x) + (v6.x + v7.x));
            acc.y += (v0.y + v1.y) + (v2.y + v3.y) + ((v4.y + v5.y) + (v6.y + v7.y));
            acc.z += (v0.z + v1.z) + (v2.z + v3.z) + ((v4.z + v5.z) + (v6.z + v7.z));
            acc.w += (v0.w + v1.w) + (v2.w + v3.w) + ((v4.w + v5.w) + (v6.w + v7.w));
        }
        for (; k < cnt; k++) {
            int s = g_esrc[start + k];
            float4 v = *(const float4*)&g_bufA[(size_t)s * DIM + lane * 4];
            acc.x += v.x; acc.y += v.y; acc.z += v.z; acc.w += v.w;
        }

        float di = rsqrtf((float)(cnt + 1));
        float4 o;
        o.x = fmaxf(fmaf(acc.x, di, b.x), 0.0f);
        o.y = fmaxf(fmaf(acc.y, di, b.y), 0.0f);
        o.z = fmaxf(fmaf(acc.z, di, b.z), 0.0f);
        o.w = fmaxf(fmaf(acc.w, di, b.w), 0.0f);
        *(float4*)&g_bufB[(size_t)n * DIM + lane * 4] = o;

        if (POOL) {
            int g = g_batch[n];
            red_add_v4(&g_sums[g * DIM + lane * 4], o);
        }
    }
}

// ---------------- final FC ----------------
__global__ void k_final(const float* __restrict__ Wfc, const float* __restrict__ bfc,
                        float* __restrict__ out) {
    int idx = blockIdx.x * blockDim.x + threadIdx.x;
    if (idx >= NG * OUTD) return;
    int g = idx / OUTD;
    int o = idx % OUTD;
    float inv = 1.0f / fmaxf(g_cnts[g], 1.0f);
    float acc = 0.0f;
#pragma unroll 8
    for (int h = 0; h < DIM; h++) acc += g_sums[g * DIM + h] * Wfc[h * OUTD + o];
    out[idx] = acc * inv + bfc[o];
}

// ---------------- launch ----------------
extern "C" void kernel_launch(void* const* d_in, const int* in_sizes, int n_in,
                              void* d_out, int out_size) {
    const float* x     = (const float*)d_in[0];
    const void*  ei    = d_in[1];
    const void*  batch = d_in[2];
    const float* W1    = (const float*)d_in[3];
    const float* b1    = (const float*)d_in[4];
    const float* W2    = (const float*)d_in[5];
    const float* b2    = (const float*)d_in[6];
    const float* Wfc   = (const float*)d_in[7];
    const float* bfc   = (const float*)d_in[8];
    float* out = (float*)d_out;

    const int gemm_blocks = (N_NODES + 127) / 128;  // 391
    const int gemm_smem   = 128 * 132 * 4;          // 67584 B

    // unconditional (no static guard -- harness rule): idempotent, not a stream op
    cudaFuncSetAttribute(k_gemm, cudaFuncAttributeMaxDynamicSharedMemorySize, gemm_smem);

    // launch order puts k_gemm (layer 1) at launch #4 for ncu -s capture
    k_init<<<256, 256>>>(ei);                       // 1
    k_convert<<<1024, 256>>>(ei, batch);            // 2
    k_scan1<<<NBLK, SCAN_B>>>();                    // 3
    k_gemm<<<gemm_blocks, 256, gemm_smem>>>(x, W1); // 4  <- profiled
    k_scan2<<<1, 32>>>();                           // 5
    k_cursor<<<196, 256>>>();                       // 6
    k_bucket<<<1024, 256>>>();                      // 7
    k_agg<false><<<2368, 256>>>(b1);                // 8
    k_gemm<<<gemm_blocks, 256, gemm_smem>>>(nullptr, W2);  // 9
    k_agg<true><<<2368, 256>>>(b2);                 // 10
    k_final<<<4, 256>>>(Wfc, bfc, out);             // 11
}

// round 9
// speedup vs baseline: 1.6433x; 1.0317x over previous
#include <cuda_runtime.h>
#include <cstdint>

#define N_NODES 50000
#define N_EDGES 800000
#define DIM     128
#define NG      64
#define OUTD    16
#define SCAN_B  1024
#define NBLK    ((N_NODES + SCAN_B - 1) / SCAN_B)   // 49

// ---------------- scratch (static device globals; no allocation) ----------------
__device__ __align__(16) int   g_src[N_EDGES];
__device__ __align__(16) int   g_dst[N_EDGES];
__device__ __align__(16) int   g_esrc[N_EDGES];     // bucketed-by-dst src list
__device__ __align__(16) int   g_batch[N_NODES];
__device__ __align__(16) int   g_ecnt[N_NODES];     // in-degree (edges only)
__device__ __align__(16) int   g_off[N_NODES];      // block-local exclusive scan
__device__ __align__(16) int   g_rowstart[N_NODES]; // final CSR row start
__device__ __align__(16) int   g_cursor[N_NODES];   // bucket-fill cursors
__device__ int   g_bsum[NBLK];
__device__ int   g_bo[NBLK];
__device__ __align__(128) float g_bufA[(size_t)N_NODES * DIM];  // h*dis (gather source)
__device__ __align__(128) float g_bufB[(size_t)N_NODES * DIM];  // layer output
__device__ __align__(16) float g_sums[NG * DIM];
__device__ __align__(16) float g_cnts[NG];
__device__ int g_is64;

// ---------------- init + dtype detect ----------------
__global__ void k_init(const void* ei) {
    int i  = blockIdx.x * blockDim.x + threadIdx.x;
    if (i == 0) {
        const unsigned long long* p = (const unsigned long long*)ei;
        bool is64 = true;
        for (int j = 0; j < 8; j++)
            if (p[j] >= (unsigned long long)N_NODES) is64 = false;
        g_is64 = is64 ? 1 : 0;
    }
    int st = gridDim.x * blockDim.x;
    for (int n = i; n < N_NODES; n += st) g_ecnt[n] = 0;
    for (int n = i; n < NG * DIM; n += st) g_sums[n] = 0.0f;
    for (int n = i; n < NG; n += st) g_cnts[n] = 0.0f;
}

// ---------------- convert indices + degree histogram + graph counts ----------------
__global__ void k_convert(const void* ei, const void* batch) {
    int i  = blockIdx.x * blockDim.x + threadIdx.x;
    int st = gridDim.x * blockDim.x;
    const bool is64 = (g_is64 != 0);
    for (int e = i; e < N_EDGES; e += st) {
        int s, d;
        if (is64) {
            s = (int)((const long long*)ei)[e];
            d = (int)((const long long*)ei)[N_EDGES + e];
        } else {
            s = ((const int*)ei)[e];
            d = ((const int*)ei)[N_EDGES + e];
        }
        g_src[e] = s;
        g_dst[e] = d;
        atomicAdd(&g_ecnt[d], 1);
    }
    for (int n = i; n < N_NODES; n += st) {
        int b = is64 ? (int)((const long long*)batch)[n]
                     : ((const int*)batch)[n];
        g_batch[n] = b;
        atomicAdd(&g_cnts[b], 1.0f);
    }
}

// ---------------- scan phase 1: per-block exclusive scan of ecnt ----------------
__global__ __launch_bounds__(SCAN_B) void k_scan1() {
    __shared__ int sh[SCAN_B];
    int b = blockIdx.x, t = threadIdx.x;
    int i = b * SCAN_B + t;
    int v = (i < N_NODES) ? g_ecnt[i] : 0;
    sh[t] = v;
    __syncthreads();
    for (int s = 1; s < SCAN_B; s <<= 1) {
        int x = (t >= s) ? sh[t - s] : 0;
        __syncthreads();
        sh[t] += x;
        __syncthreads();
    }
    if (i < N_NODES) g_off[i] = sh[t] - v;   // exclusive
    if (t == SCAN_B - 1) g_bsum[b] = sh[t];
}

// ---------------- scan phase 2 ----------------
__global__ void k_scan2() {
    if (threadIdx.x == 0) {
        int a = 0;
        for (int i = 0; i < NBLK; i++) { g_bo[i] = a; a += g_bsum[i]; }
    }
}

// ---------------- final offsets + cursors ----------------
__global__ void k_cursor() {
    int i  = blockIdx.x * blockDim.x + threadIdx.x;
    int st = gridDim.x * blockDim.x;
    for (int n = i; n < N_NODES; n += st) {
        int base = g_off[n] + g_bo[n >> 10];
        g_rowstart[n] = base;
        g_cursor[n]   = base;
    }
}

// ---------------- bucket fill ----------------
__global__ void k_bucket() {
    int i  = blockIdx.x * blockDim.x + threadIdx.x;
    int st = gridDim.x * blockDim.x;
    for (int e = i; e < N_EDGES; e += st) {
        int d = g_dst[e];
        int pos = atomicAdd(&g_cursor[d], 1);
        g_esrc[pos] = g_src[e];
    }
}

// ---------------- tf32 helpers ----------------
__device__ __forceinline__ unsigned f2tf32(float f) {
    unsigned u;
    asm("cvt.rna.tf32.f32 %0, %1;" : "=r"(u) : "f"(f));
    return u;
}

__device__ __forceinline__ void mma_tf32(float& c0, float& c1, float& c2, float& c3,
                                         unsigned a0, unsigned a1, unsigned a2, unsigned a3,
                                         unsigned b0, unsigned b1) {
    asm volatile(
        "mma.sync.aligned.m16n8k8.row.col.f32.tf32.tf32.f32 "
        "{%0,%1,%2,%3}, {%4,%5,%6,%7}, {%8,%9}, {%0,%1,%2,%3};"
        : "+f"(c0), "+f"(c1), "+f"(c2), "+f"(c3)
        : "r"(a0), "r"(a1), "r"(a2), "r"(a3), "r"(b0), "r"(b1));
}

// ---------------- GEMM: bufA = (A @ W) * dis[row]  (tf32, pre-packed B frags) ----------------
// 4 warps/block, each warp: 32 rows (two m16 tiles) x 128 cols. Block = 128 rows.
// Smem holds PRE-PACKED B fragments: Bf[kc][nt][lane] = uint2{ tf32(W[kc*8+t][nt*8+g]),
// tf32(W[kc*8+t+4][nt*8+g]) } with lane = g*4+t. Main-loop B access = one lane-linear
// LDS.64 (conflict-free) feeding TWO MMAs -> MMA:LDS = 2:1 (was 1:2 scalar in R7).
// Ain==nullptr -> read g_bufB (device-side symbol; host can't pass __device__ arrays).
__global__ __launch_bounds__(128) void k_gemm(const float* Ain,
                                              const float* __restrict__ W) {
    extern __shared__ uint2 Bf[];   // 16*16*32 uint2 = 65536 B
    const float* A = Ain ? Ain : g_bufB;
    const int tid  = threadIdx.x;
    const int w    = tid >> 5;
    const int lane = tid & 31;
    const int g    = lane >> 2;   // fragment row group 0..7
    const int t    = lane & 3;    // thread-in-group 0..3

    // stage pre-packed B fragments
    for (int idx = tid; idx < 16 * 16 * 32; idx += 128) {
        int l  = idx & 31;
        int nt = (idx >> 5) & 15;
        int kc = idx >> 9;
        int gg = l >> 2, tt = l & 3;
        int n  = nt * 8 + gg;
        int k0 = kc * 8 + tt;
        uint2 b;
        b.x = f2tf32(W[(size_t)k0 * DIM + n]);
        b.y = f2tf32(W[(size_t)(k0 + 4) * DIM + n]);
        Bf[idx] = b;
    }
    __syncthreads();

    // rows handled by this thread: tile0 -> r0, r0+8 ; tile1 -> r0+16, r0+24
    const int rbase = blockIdx.x * 128 + w * 32;
    const int r0 = rbase + g;
    const int r1 = rbase + g + 8;
    const int r2 = rbase + g + 16;
    const int r3 = rbase + g + 24;
    const bool ok0 = r0 < N_NODES, ok1 = r1 < N_NODES;
    const bool ok2 = r2 < N_NODES, ok3 = r3 < N_NODES;
    const float* p0 = A + (size_t)r0 * DIM;
    const float* p1 = A + (size_t)r1 * DIM;
    const float* p2 = A + (size_t)r2 * DIM;
    const float* p3 = A + (size_t)r3 * DIM;

    float acc[2][16][4];
#pragma unroll
    for (int ti = 0; ti < 2; ti++)
#pragma unroll
        for (int nt = 0; nt < 16; nt++)
#pragma unroll
            for (int j = 0; j < 4; j++) acc[ti][nt][j] = 0.0f;

#pragma unroll 4
    for (int kc = 0; kc < 16; kc++) {
        const int K0 = kc * 8;
        // A fragments for both m16 tiles (8 LDG.32 + cvt)
        unsigned a00 = ok0 ? f2tf32(p0[K0 + t])     : 0u;
        unsigned a01 = ok1 ? f2tf32(p1[K0 + t])     : 0u;
        unsigned a02 = ok0 ? f2tf32(p0[K0 + t + 4]) : 0u;
        unsigned a03 = ok1 ? f2tf32(p1[K0 + t + 4]) : 0u;
        unsigned a10 = ok2 ? f2tf32(p2[K0 + t])     : 0u;
        unsigned a11 = ok3 ? f2tf32(p3[K0 + t])     : 0u;
        unsigned a12 = ok2 ? f2tf32(p2[K0 + t + 4]) : 0u;
        unsigned a13 = ok3 ? f2tf32(p3[K0 + t + 4]) : 0u;
#pragma unroll
        for (int nt = 0; nt < 16; nt++) {
            uint2 b = Bf[(kc * 16 + nt) * 32 + lane];  // LDS.64 conflict-free
            mma_tf32(acc[0][nt][0], acc[0][nt][1], acc[0][nt][2], acc[0][nt][3],
                     a00, a01, a02, a03, b.x, b.y);
            mma_tf32(acc[1][nt][0], acc[1][nt][1], acc[1][nt][2], acc[1][nt][3],
                     a10, a11, a12, a13, b.x, b.y);
        }
    }

    // epilogue: scale by dis = rsqrt(deg), deg = ecnt + 1; cols {2t, 2t+1} per nt
    float d0 = ok0 ? rsqrtf((float)(g_ecnt[r0] + 1)) : 0.0f;
    float d1 = ok1 ? rsqrtf((float)(g_ecnt[r1] + 1)) : 0.0f;
    float d2 = ok2 ? rsqrtf((float)(g_ecnt[r2] + 1)) : 0.0f;
    float d3 = ok3 ? rsqrtf((float)(g_ecnt[r3] + 1)) : 0.0f;
#pragma unroll
    for (int nt = 0; nt < 16; nt++) {
        int col = nt * 8 + 2 * t;
        if (ok0) *(float2*)&g_bufA[(size_t)r0 * DIM + col] =
            make_float2(acc[0][nt][0] * d0, acc[0][nt][1] * d0);
        if (ok1) *(float2*)&g_bufA[(size_t)r1 * DIM + col] =
            make_float2(acc[0][nt][2] * d1, acc[0][nt][3] * d1);
        if (ok2) *(float2*)&g_bufA[(size_t)r2 * DIM + col] =
            make_float2(acc[1][nt][0] * d2, acc[1][nt][1] * d2);
        if (ok3) *(float2*)&g_bufA[(size_t)r3 * DIM + col] =
            make_float2(acc[1][nt][2] * d3, acc[1][nt][3] * d3);
    }
}

// ---------------- RED.v4 helper ----------------
__device__ __forceinline__ void red_add_v4(float* p, float4 v) {
    unsigned long long gp = (unsigned long long)__cvta_generic_to_global(p);
    asm volatile("red.global.add.v4.f32 [%0], {%1,%2,%3,%4};"
                 :: "l"(gp), "f"(v.x), "f"(v.y), "f"(v.z), "f"(v.w)
                 : "memory");
}

// ---------------- aggregation: warp per node, CSR gather ----------------
template <bool POOL>
__global__ __launch_bounds__(256) void k_agg(const float* __restrict__ bias) {
    int gtid = blockIdx.x * blockDim.x + threadIdx.x;
    int warp = gtid >> 5;
    int lane = gtid & 31;
    int nw   = (gridDim.x * blockDim.x) >> 5;
    float4 b = *(const float4*)&bias[lane * 4];

    for (int n = warp; n < N_NODES; n += nw) {
        int start = g_rowstart[n];
        int cnt   = g_ecnt[n];
        float4 acc = *(const float4*)&g_bufA[(size_t)n * DIM + lane * 4];  // self loop

        int k = 0;
        for (; k + 8 <= cnt; k += 8) {
            int s0 = g_esrc[start + k + 0];
            int s1 = g_esrc[start + k + 1];
            int s2 = g_esrc[start + k + 2];
            int s3 = g_esrc[start + k + 3];
            int s4 = g_esrc[start + k + 4];
            int s5 = g_esrc[start + k + 5];
            int s6 = g_esrc[start + k + 6];
            int s7 = g_esrc[start + k + 7];
            float4 v0 = *(const float4*)&g_bufA[(size_t)s0 * DIM + lane * 4];
            float4 v1 = *(const float4*)&g_bufA[(size_t)s1 * DIM + lane * 4];
            float4 v2 = *(const float4*)&g_bufA[(size_t)s2 * DIM + lane * 4];
            float4 v3 = *(const float4*)&g_bufA[(size_t)s3 * DIM + lane * 4];
            float4 v4 = *(const float4*)&g_bufA[(size_t)s4 * DIM + lane * 4];
            float4 v5 = *(const float4*)&g_bufA[(size_t)s5 * DIM + lane * 4];
            float4 v6 = *(const float4*)&g_bufA[(size_t)s6 * DIM + lane * 4];
            float4 v7 = *(const float4*)&g_bufA[(size_t)s7 * DIM + lane * 4];
            acc.x += (v0.x + v1.x) + (v2.x + v3.x) + ((v4.x + v5.x) + (v6.x + v7.x));
            acc.y += (v0.y + v1.y) + (v2.y + v3.y) + ((v4.y + v5.y) + (v6.y + v7.y));
            acc.z += (v0.z + v1.z) + (v2.z + v3.z) + ((v4.z + v5.z) + (v6.z + v7.z));
            acc.w += (v0.w + v1.w) + (v2.w + v3.w) + ((v4.w + v5.w) + (v6.w + v7.w));
        }
        for (; k < cnt; k++) {
            int s = g_esrc[start + k];
            float4 v = *(const float4*)&g_bufA[(size_t)s * DIM + lane * 4];
            acc.x += v.x; acc.y += v.y; acc.z += v.z; acc.w += v.w;
        }

        float di = rsqrtf((float)(cnt + 1));
        float4 o;
        o.x = fmaxf(fmaf(acc.x, di, b.x), 0.0f);
        o.y = fmaxf(fmaf(acc.y, di, b.y), 0.0f);
        o.z = fmaxf(fmaf(acc.z, di, b.z), 0.0f);
        o.w = fmaxf(fmaf(acc.w, di, b.w), 0.0f);
        *(float4*)&g_bufB[(size_t)n * DIM + lane * 4] = o;

        if (POOL) {
            int g = g_batch[n];
            red_add_v4(&g_sums[g * DIM + lane * 4], o);
        }
    }
}

// ---------------- final FC ----------------
__global__ void k_final(const float* __restrict__ Wfc, const float* __restrict__ bfc,
                        float* __restrict__ out) {
    int idx = blockIdx.x * blockDim.x + threadIdx.x;
    if (idx >= NG * OUTD) return;
    int g = idx / OUTD;
    int o = idx % OUTD;
    float inv = 1.0f / fmaxf(g_cnts[g], 1.0f);
    float acc = 0.0f;
#pragma unroll 8
    for (int h = 0; h < DIM; h++) acc += g_sums[g * DIM + h] * Wfc[h * OUTD + o];
    out[idx] = acc * inv + bfc[o];
}

// ---------------- launch ----------------
extern "C" void kernel_launch(void* const* d_in, const int* in_sizes, int n_in,
                              void* d_out, int out_size) {
    const float* x     = (const float*)d_in[0];
    const void*  ei    = d_in[1];
    const void*  batch = d_in[2];
    const float* W1    = (const float*)d_in[3];
    const float* b1    = (const float*)d_in[4];
    const float* W2    = (const float*)d_in[5];
    const float* b2    = (const float*)d_in[6];
    const float* Wfc   = (const float*)d_in[7];
    const float* bfc   = (const float*)d_in[8];
    float* out = (float*)d_out;

    const int gemm_blocks = (N_NODES + 127) / 128;  // 391
    const int gemm_smem   = 16 * 16 * 32 * 8;       // 65536 B

    // unconditional (no static guard -- harness rule): idempotent, not a stream op
    cudaFuncSetAttribute(k_gemm, cudaFuncAttributeMaxDynamicSharedMemorySize, gemm_smem);

    // launch order puts k_gemm (layer 1) at the ncu-captured slot (#4)
    k_init<<<256, 256>>>(ei);                       // 1
    k_convert<<<1024, 256>>>(ei, batch);            // 2
    k_scan1<<<NBLK, SCAN_B>>>();                    // 3
    k_gemm<<<gemm_blocks, 128, gemm_smem>>>(x, W1); // 4  <- profiled
    k_scan2<<<1, 32>>>();                           // 5
    k_cursor<<<196, 256>>>();                       // 6
    k_bucket<<<1024, 256>>>();                      // 7
    k_agg<false><<<2368, 256>>>(b1);                // 8
    k_gemm<<<gemm_blocks, 128, gemm_smem>>>(nullptr, W2);  // 9
    k_agg<true><<<2368, 256>>>(b2);                 // 10
    k_final<<<4, 256>>>(Wfc, bfc, out);             // 11
}